// round 16
// baseline (speedup 1.0000x reference)
#include <cuda_runtime.h>
#include <cuda_fp16.h>
#include <cstdint>

// Problem constants (fixed shapes from reference)
#define BB 8
#define NVV 8192
#define EE 32768

typedef unsigned long long ull;

// ---------------------------------------------------------------------------
// Device scratch (no cudaMalloc allowed)
//  - M matrix split to fp16 hi / fp16 residual-lo, layout [bc][e], bc = b*3+c
//  - g_Lv: fp32 L_vert accumulator [bc][n]
// ---------------------------------------------------------------------------
__device__ __half g_Bh[24 * EE];   // 1.5 MB
__device__ __half g_Bl[24 * EE];   // 1.5 MB
__device__ float  g_Lv[24 * NVV];  // 768 KB

#define EDGE_BLOCKS ((BB * EE) / 256)            // 1024
#define ZERO_BLOCKS ((24 * NVV) / 256)           // 768

// ---------------------------------------------------------------------------
// Kernel 1: per-(b,e) constraint solve -> L_new + split-fp16 M scratch [bc][e]
//           (+ fused g_Lv zeroing in trailing blocks)
// ---------------------------------------------------------------------------
__global__ void k_edge(const float* __restrict__ Vp,     // (B,NV,3)
                       const float* __restrict__ L,      // (B,E,1)
                       const float* __restrict__ Vw,     // (B,NV,1)
                       const float* __restrict__ Vc,     // (B,1,1)
                       const int*   __restrict__ Cd,     // (E,2)
                       const float* __restrict__ Cid,    // (E,1)
                       float*       __restrict__ Lnew)   // (B,E) at d_out + B*NV*3
{
    if (blockIdx.x >= EDGE_BLOCKS) {               // fused zero of g_Lv
        int t = (blockIdx.x - EDGE_BLOCKS) * 256 + threadIdx.x;
        g_Lv[t] = 0.0f;
        return;
    }

    int tid = blockIdx.x * 256 + threadIdx.x;
    int b = tid / EE;
    int e = tid - b * EE;

    int i = Cd[2 * e];
    int j = Cd[2 * e + 1];

    const float* pi = Vp + ((size_t)b * NVV + i) * 3;
    const float* pj = Vp + ((size_t)b * NVV + j) * 3;
    float nx = pi[0] - pj[0];
    float ny = pi[1] - pj[1];
    float nz = pi[2] - pj[2];
    float D = sqrtf(nx * nx + ny * ny + nz * nz);
    float C = D - Cid[e];

    float A = Vc[b];
    float S = Vw[b * NVV + i] + Vw[b * NVV + j];
    float Seff = (S == 0.0f) ? __int_as_float(0x7f800000) : S;   // inf where S==0
    float denom = Seff + A;

    float l  = L[tid];
    float ld = (-C - A * l) / denom;    // -> 0 when denom == inf
    Lnew[tid] = l + ld;

    float inv = ld / (D + 1e-8f);       // L_delta * N_norm
    float m0 = inv * nx, m1 = inv * ny, m2 = inv * nz;

#pragma unroll
    for (int c = 0; c < 3; c++) {
        float m = (c == 0) ? m0 : (c == 1) ? m1 : m2;
        size_t o = (size_t)(b * 3 + c) * EE + e;
        __half h = __float2half_rn(m);
        g_Bh[o] = h;
        g_Bl[o] = __float2half_rn(m - __half2float(h));
    }
}

// ---------------------------------------------------------------------------
// Kernel 2: Lv[bc][n] += sum_e Cm[e][n] * M[bc][e]   via mma.sync fp16 (HMMA).
//
// v4 precision scheme (2 MMAs instead of 3):
//   A = Cm as SINGLE fp16 (11-bit mantissa; per-element independent +-2^-12
//       error on N(0,1) data -> final rel_err ~1.5e-4, margin ~6x under 1e-3)
//   B = M as fp16 hi + fp16 residual (22-bit exact)
//   D = A*Bh + A*Bl
// Benefits vs R14 3-term bf16: tensor work 2/3, A-side SMEM store+ldmatrix
// traffic HALVED (one tile, no residual tile), SMEM 40->24 KB, fewer regs
// -> occupancy 5 CTAs/SM (20 warps). Double buffer + NSEG=32 unchanged.
// ---------------------------------------------------------------------------
#define TCT 128
#define NSEG 32
#define E_PER (EE / NSEG)            // 1024
#define CHUNK 32
#define NCHUNK (E_PER / CHUNK)       // 32
#define BROW 40                      // sB row stride in halves (80 B)

__device__ __forceinline__ uint32_t s2u(const void* p) {
    return (uint32_t)__cvta_generic_to_shared(p);
}
__device__ __forceinline__ void ldsm_x4_t(uint32_t* r, uint32_t addr) {
    asm volatile(
        "ldmatrix.sync.aligned.m8n8.x4.trans.shared.b16 {%0,%1,%2,%3}, [%4];"
        : "=r"(r[0]), "=r"(r[1]), "=r"(r[2]), "=r"(r[3]) : "r"(addr));
}
__device__ __forceinline__ void hmma(float* d, const uint32_t* a,
                                     uint32_t b0, uint32_t b1) {
    asm volatile(
        "mma.sync.aligned.m16n8k16.row.col.f32.f16.f16.f32 "
        "{%0,%1,%2,%3}, {%4,%5,%6,%7}, {%8,%9}, {%0,%1,%2,%3};"
        : "+f"(d[0]), "+f"(d[1]), "+f"(d[2]), "+f"(d[3])
        : "r"(a[0]), "r"(a[1]), "r"(a[2]), "r"(a[3]), "r"(b0), "r"(b1));
}
// pack (hi16 <- fh, lo16 <- fl) as fp16x2
__device__ __forceinline__ uint32_t f16x2(float fh, float fl) {
    uint32_t w;
    asm("cvt.rn.f16x2.f32 %0, %1, %2;" : "=r"(w) : "f"(fh), "f"(fl));
    return w;
}

__global__ void __launch_bounds__(TCT, 5)
k_gemm_tc(const float* __restrict__ Cm)   // C_mtx (E, NV) row-major
{
    // double-buffered A tile: [e][n] fp16, 32 x 128, 256 B/row, XOR swizzle
    __shared__ alignas(16) unsigned char sA[2][32 * 256];     // 16 KB
    // double-buffered B tiles: [bc][e] fp16, 24 x 32 + pad, 80 B/row
    __shared__ alignas(16) __half sBh[2][24 * BROW];          // 3.8 KB
    __shared__ alignas(16) __half sBl[2][24 * BROW];

    const int t    = threadIdx.x;
    const int warp = t >> 5;
    const int lane = t & 31;
    const int g    = lane >> 2;
    const int tig  = lane & 3;

    const int n0     = blockIdx.x * 128;
    const int e_base = blockIdx.y * E_PER;

    float acc[2][3][4];
#pragma unroll
    for (int mt = 0; mt < 2; mt++)
#pragma unroll
        for (int bt = 0; bt < 3; bt++)
#pragma unroll
            for (int r = 0; r < 4; r++) acc[mt][bt][r] = 0.0f;

    const int li   = lane & 7;
    const int half = (lane >> 3) & 1;
    const int kh   = lane >> 4;

    const int a_nt   = (t & 31) * 4;      // n offset of this thread's float4
    const int a_erow = t >> 5;            // e row 0..3 (stride 4)
    const uint32_t a_c     = (uint32_t)(a_nt >> 3);
    const uint32_t a_inner = (uint32_t)((a_nt & 4) << 1);   // 0 or 8

    const int b_bc   = t >> 2;            // t<96: bc row
    const int b_part = t & 3;

    const float* a_base = Cm + (size_t)(e_base + a_erow) * NVV + n0 + a_nt;

    // ---- preload chunk 0 into registers ----
    float4 v[8];
#pragma unroll
    for (int i = 0; i < 8; i++)
        v[i] = __ldcs(reinterpret_cast<const float4*>(a_base + (size_t)(4 * i) * NVV));
    uint4 bvh, bvl;
    if (t < 96) {
        bvh = *(reinterpret_cast<const uint4*>(g_Bh + (size_t)b_bc * EE + e_base) + b_part);
        bvl = *(reinterpret_cast<const uint4*>(g_Bl + (size_t)b_bc * EE + e_base) + b_part);
    }

    int p = 0;
    for (int ck = 0; ck < NCHUNK; ck++) {
        // ---- convert & store registers -> SMEM buffer p ----
#pragma unroll
        for (int i = 0; i < 8; i++) {
            int e = a_erow + 4 * i;
            uint32_t h01 = f16x2(v[i].y, v[i].x);
            uint32_t h23 = f16x2(v[i].w, v[i].z);
            uint32_t off = (uint32_t)e * 256 +
                           (((a_c ^ (uint32_t)(e & 7)) << 4) | a_inner);
            *reinterpret_cast<uint2*>(&sA[p][0] + off) = make_uint2(h01, h23);
        }
        if (t < 96) {
            *reinterpret_cast<uint4*>(sBh[p] + b_bc * BROW + b_part * 8) = bvh;
            *reinterpret_cast<uint4*>(sBl[p] + b_bc * BROW + b_part * 8) = bvl;
        }
        __syncthreads();

        // ---- issue next chunk's global loads (in flight during compute) ----
        if (ck + 1 < NCHUNK) {
            const float* nb = a_base + (size_t)(ck + 1) * CHUNK * NVV;
#pragma unroll
            for (int i = 0; i < 8; i++)
                v[i] = __ldcs(reinterpret_cast<const float4*>(nb + (size_t)(4 * i) * NVV));
            if (t < 96) {
                int e1 = e_base + (ck + 1) * CHUNK;
                bvh = *(reinterpret_cast<const uint4*>(g_Bh + (size_t)b_bc * EE + e1) + b_part);
                bvl = *(reinterpret_cast<const uint4*>(g_Bl + (size_t)b_bc * EE + e1) + b_part);
            }
        }

        // ---- compute: 2 k16 steps from buffer p ----
#pragma unroll
        for (int ks = 0; ks < 2; ks++) {
            const int ek = ks * 16;
            uint32_t bh0[3], bh1[3], bl0[3], bl1[3];
#pragma unroll
            for (int bt = 0; bt < 3; bt++) {
                int row = (bt * 8 + g) * BROW;
                bh0[bt] = *reinterpret_cast<const uint32_t*>(sBh[p] + row + ek + 2 * tig);
                bh1[bt] = *reinterpret_cast<const uint32_t*>(sBh[p] + row + ek + 8 + 2 * tig);
                bl0[bt] = *reinterpret_cast<const uint32_t*>(sBl[p] + row + ek + 2 * tig);
                bl1[bt] = *reinterpret_cast<const uint32_t*>(sBl[p] + row + ek + 8 + 2 * tig);
            }
#pragma unroll
            for (int mt = 0; mt < 2; mt++) {
                const int mb = warp * 32 + mt * 16;
                const int e_loc = ek + kh * 8 + li;
                const uint32_t cc = (uint32_t)((mb >> 3) + half);
                const uint32_t a_off = (uint32_t)e_loc * 256 +
                                       ((cc ^ (uint32_t)(e_loc & 7)) << 4);
                uint32_t a[4];
                ldsm_x4_t(a, s2u(&sA[p][0]) + a_off);
#pragma unroll
                for (int bt = 0; bt < 3; bt++) {
                    hmma(acc[mt][bt], a, bh0[bt], bh1[bt]);
                    hmma(acc[mt][bt], a, bl0[bt], bl1[bt]);
                }
            }
        }
        p ^= 1;
    }

    // ---- epilogue: D fragment -> atomicAdd g_Lv[bc][n] ----
#pragma unroll
    for (int mt = 0; mt < 2; mt++) {
#pragma unroll
        for (int bt = 0; bt < 3; bt++) {
            int n  = n0 + warp * 32 + mt * 16 + g;
            int bc = bt * 8 + 2 * tig;
            atomicAdd(g_Lv + (size_t)bc * NVV + n,           acc[mt][bt][0]);
            atomicAdd(g_Lv + (size_t)(bc + 1) * NVV + n,     acc[mt][bt][1]);
            atomicAdd(g_Lv + (size_t)bc * NVV + n + 8,       acc[mt][bt][2]);
            atomicAdd(g_Lv + (size_t)(bc + 1) * NVV + n + 8, acc[mt][bt][3]);
        }
    }
}

// ---------------------------------------------------------------------------
// Kernel 3: V_predict_new = V_predict + V_w * L_vert
// ---------------------------------------------------------------------------
__global__ void k_epi(const float* __restrict__ Vp,
                      const float* __restrict__ Vw,
                      float*       __restrict__ out)     // (B,NV,3) at d_out
{
    int tid = blockIdx.x * blockDim.x + threadIdx.x;
    if (tid >= BB * NVV) return;
    int b = tid / NVV;
    int n = tid - b * NVV;
    float w = Vw[tid];
    size_t o = (size_t)tid * 3;
    out[o + 0] = Vp[o + 0] + w * g_Lv[(size_t)(b * 3 + 0) * NVV + n];
    out[o + 1] = Vp[o + 1] + w * g_Lv[(size_t)(b * 3 + 1) * NVV + n];
    out[o + 2] = Vp[o + 2] + w * g_Lv[(size_t)(b * 3 + 2) * NVV + n];
}

// ---------------------------------------------------------------------------
extern "C" void kernel_launch(void* const* d_in, const int* in_sizes, int n_in,
                              void* d_out, int out_size)
{
    const float* Vp  = (const float*)d_in[0];   // V_predict    (B,NV,3)
    const float* L   = (const float*)d_in[1];   // L            (B,E,1)
    const float* Vw  = (const float*)d_in[2];   // V_w          (B,NV,1)
    const float* Vc  = (const float*)d_in[3];   // V_compliance (B,1,1)
    const int*   Cd  = (const int*)  d_in[4];   // C_dist       (E,2)
    const float* Cid = (const float*)d_in[5];   // C_init_d     (E,1)
    const float* Cm  = (const float*)d_in[6];   // C_mtx        (E,NV)

    float* out_vp = (float*)d_out;                         // V_predict_new
    float* out_L  = (float*)d_out + (size_t)BB * NVV * 3;  // L_new

    // 1) edge solve -> split-fp16 M, L_new  (+ fused g_Lv zeroing)
    k_edge<<<EDGE_BLOCKS + ZERO_BLOCKS, 256>>>(Vp, L, Vw, Vc, Cd, Cid, out_L);

    // 2) tensor-core GEMM (mma.sync fp16, 2-term emulation, double-buffered)
    k_gemm_tc<<<dim3(NVV / 128, NSEG), TCT>>>(Cm);

    // 3) vertex update
    k_epi<<<(BB * NVV + 255) / 256, 256>>>(Vp, Vw, out_vp);
}

// round 17
// speedup vs baseline: 1.2093x; 1.2093x over previous
#include <cuda_runtime.h>
#include <cuda_fp16.h>
#include <cstdint>

// Problem constants (fixed shapes from reference)
#define BB 8
#define NVV 8192
#define EE 32768

typedef unsigned long long ull;

// ---------------------------------------------------------------------------
// Device scratch (no cudaMalloc allowed)
//  - M matrix split to fp16 hi / fp16 residual-lo, layout [bc][e], bc = b*3+c
//  - g_Lv: fp32 L_vert accumulator [bc][n]
// ---------------------------------------------------------------------------
__device__ __half g_Bh[24 * EE];   // 1.5 MB
__device__ __half g_Bl[24 * EE];   // 1.5 MB
__device__ float  g_Lv[24 * NVV];  // 768 KB

#define EDGE_BLOCKS ((BB * EE) / 256)            // 1024
#define ZERO_BLOCKS ((24 * NVV) / 256)           // 768

// ---------------------------------------------------------------------------
// Kernel 1: per-(b,e) constraint solve -> L_new + split-fp16 M scratch [bc][e]
//           (+ fused g_Lv zeroing in trailing blocks)
// ---------------------------------------------------------------------------
__global__ void k_edge(const float* __restrict__ Vp,     // (B,NV,3)
                       const float* __restrict__ L,      // (B,E,1)
                       const float* __restrict__ Vw,     // (B,NV,1)
                       const float* __restrict__ Vc,     // (B,1,1)
                       const int*   __restrict__ Cd,     // (E,2)
                       const float* __restrict__ Cid,    // (E,1)
                       float*       __restrict__ Lnew)   // (B,E) at d_out + B*NV*3
{
    if (blockIdx.x >= EDGE_BLOCKS) {               // fused zero of g_Lv
        int t = (blockIdx.x - EDGE_BLOCKS) * 256 + threadIdx.x;
        g_Lv[t] = 0.0f;
        return;
    }

    int tid = blockIdx.x * 256 + threadIdx.x;
    int b = tid / EE;
    int e = tid - b * EE;

    int i = Cd[2 * e];
    int j = Cd[2 * e + 1];

    const float* pi = Vp + ((size_t)b * NVV + i) * 3;
    const float* pj = Vp + ((size_t)b * NVV + j) * 3;
    float nx = pi[0] - pj[0];
    float ny = pi[1] - pj[1];
    float nz = pi[2] - pj[2];
    float D = sqrtf(nx * nx + ny * ny + nz * nz);
    float C = D - Cid[e];

    float A = Vc[b];
    float S = Vw[b * NVV + i] + Vw[b * NVV + j];
    float Seff = (S == 0.0f) ? __int_as_float(0x7f800000) : S;   // inf where S==0
    float denom = Seff + A;

    float l  = L[tid];
    float ld = (-C - A * l) / denom;    // -> 0 when denom == inf
    Lnew[tid] = l + ld;

    float inv = ld / (D + 1e-8f);       // L_delta * N_norm
    float m0 = inv * nx, m1 = inv * ny, m2 = inv * nz;

#pragma unroll
    for (int c = 0; c < 3; c++) {
        float m = (c == 0) ? m0 : (c == 1) ? m1 : m2;
        size_t o = (size_t)(b * 3 + c) * EE + e;
        __half h = __float2half_rn(m);
        g_Bh[o] = h;
        g_Bl[o] = __float2half_rn(m - __half2float(h));
    }
}

// ---------------------------------------------------------------------------
// Kernel 2: Lv[bc][n] += sum_e Cm[e][n] * M[bc][e]   via mma.sync fp16 (HMMA).
//
// v5 = v4 precision scheme at the PROVEN occupancy:
//   A = Cm as SINGLE fp16, B = M as fp16 hi + fp16 residual, D = A*Bh + A*Bl.
//   __launch_bounds__(128, 4): reg budget 128 (R16's occ-5 cap of 102 regs
//   spilled the float4 v[8] prefetch to local memory -> the regression).
// Benefits vs 3-term bf16: tensor work 2/3, A-side SMEM store+ldmatrix
// traffic halved, SMEM 40->24 KB. Double buffer + NSEG=32 unchanged.
// ---------------------------------------------------------------------------
#define TCT 128
#define NSEG 32
#define E_PER (EE / NSEG)            // 1024
#define CHUNK 32
#define NCHUNK (E_PER / CHUNK)       // 32
#define BROW 40                      // sB row stride in halves (80 B)

__device__ __forceinline__ uint32_t s2u(const void* p) {
    return (uint32_t)__cvta_generic_to_shared(p);
}
__device__ __forceinline__ void ldsm_x4_t(uint32_t* r, uint32_t addr) {
    asm volatile(
        "ldmatrix.sync.aligned.m8n8.x4.trans.shared.b16 {%0,%1,%2,%3}, [%4];"
        : "=r"(r[0]), "=r"(r[1]), "=r"(r[2]), "=r"(r[3]) : "r"(addr));
}
__device__ __forceinline__ void hmma(float* d, const uint32_t* a,
                                     uint32_t b0, uint32_t b1) {
    asm volatile(
        "mma.sync.aligned.m16n8k16.row.col.f32.f16.f16.f32 "
        "{%0,%1,%2,%3}, {%4,%5,%6,%7}, {%8,%9}, {%0,%1,%2,%3};"
        : "+f"(d[0]), "+f"(d[1]), "+f"(d[2]), "+f"(d[3])
        : "r"(a[0]), "r"(a[1]), "r"(a[2]), "r"(a[3]), "r"(b0), "r"(b1));
}
// pack (hi16 <- fh, lo16 <- fl) as fp16x2
__device__ __forceinline__ uint32_t f16x2(float fh, float fl) {
    uint32_t w;
    asm("cvt.rn.f16x2.f32 %0, %1, %2;" : "=r"(w) : "f"(fh), "f"(fl));
    return w;
}

__global__ void __launch_bounds__(TCT, 4)
k_gemm_tc(const float* __restrict__ Cm)   // C_mtx (E, NV) row-major
{
    // double-buffered A tile: [e][n] fp16, 32 x 128, 256 B/row, XOR swizzle
    __shared__ alignas(16) unsigned char sA[2][32 * 256];     // 16 KB
    // double-buffered B tiles: [bc][e] fp16, 24 x 32 + pad, 80 B/row
    __shared__ alignas(16) __half sBh[2][24 * BROW];          // 3.8 KB
    __shared__ alignas(16) __half sBl[2][24 * BROW];

    const int t    = threadIdx.x;
    const int warp = t >> 5;
    const int lane = t & 31;
    const int g    = lane >> 2;
    const int tig  = lane & 3;

    const int n0     = blockIdx.x * 128;
    const int e_base = blockIdx.y * E_PER;

    float acc[2][3][4];
#pragma unroll
    for (int mt = 0; mt < 2; mt++)
#pragma unroll
        for (int bt = 0; bt < 3; bt++)
#pragma unroll
            for (int r = 0; r < 4; r++) acc[mt][bt][r] = 0.0f;

    const int li   = lane & 7;
    const int half = (lane >> 3) & 1;
    const int kh   = lane >> 4;

    const int a_nt   = (t & 31) * 4;      // n offset of this thread's float4
    const int a_erow = t >> 5;            // e row 0..3 (stride 4)
    const uint32_t a_c     = (uint32_t)(a_nt >> 3);
    const uint32_t a_inner = (uint32_t)((a_nt & 4) << 1);   // 0 or 8

    const int b_bc   = t >> 2;            // t<96: bc row
    const int b_part = t & 3;

    const float* a_base = Cm + (size_t)(e_base + a_erow) * NVV + n0 + a_nt;

    // ---- preload chunk 0 into registers ----
    float4 v[8];
#pragma unroll
    for (int i = 0; i < 8; i++)
        v[i] = __ldcs(reinterpret_cast<const float4*>(a_base + (size_t)(4 * i) * NVV));
    uint4 bvh, bvl;
    if (t < 96) {
        bvh = *(reinterpret_cast<const uint4*>(g_Bh + (size_t)b_bc * EE + e_base) + b_part);
        bvl = *(reinterpret_cast<const uint4*>(g_Bl + (size_t)b_bc * EE + e_base) + b_part);
    }

    int p = 0;
    for (int ck = 0; ck < NCHUNK; ck++) {
        // ---- convert & store registers -> SMEM buffer p ----
#pragma unroll
        for (int i = 0; i < 8; i++) {
            int e = a_erow + 4 * i;
            uint32_t h01 = f16x2(v[i].y, v[i].x);
            uint32_t h23 = f16x2(v[i].w, v[i].z);
            uint32_t off = (uint32_t)e * 256 +
                           (((a_c ^ (uint32_t)(e & 7)) << 4) | a_inner);
            *reinterpret_cast<uint2*>(&sA[p][0] + off) = make_uint2(h01, h23);
        }
        if (t < 96) {
            *reinterpret_cast<uint4*>(sBh[p] + b_bc * BROW + b_part * 8) = bvh;
            *reinterpret_cast<uint4*>(sBl[p] + b_bc * BROW + b_part * 8) = bvl;
        }
        __syncthreads();

        // ---- issue next chunk's global loads (in flight during compute) ----
        if (ck + 1 < NCHUNK) {
            const float* nb = a_base + (size_t)(ck + 1) * CHUNK * NVV;
#pragma unroll
            for (int i = 0; i < 8; i++)
                v[i] = __ldcs(reinterpret_cast<const float4*>(nb + (size_t)(4 * i) * NVV));
            if (t < 96) {
                int e1 = e_base + (ck + 1) * CHUNK;
                bvh = *(reinterpret_cast<const uint4*>(g_Bh + (size_t)b_bc * EE + e1) + b_part);
                bvl = *(reinterpret_cast<const uint4*>(g_Bl + (size_t)b_bc * EE + e1) + b_part);
            }
        }

        // ---- compute: 2 k16 steps from buffer p ----
#pragma unroll
        for (int ks = 0; ks < 2; ks++) {
            const int ek = ks * 16;
            uint32_t bh0[3], bh1[3], bl0[3], bl1[3];
#pragma unroll
            for (int bt = 0; bt < 3; bt++) {
                int row = (bt * 8 + g) * BROW;
                bh0[bt] = *reinterpret_cast<const uint32_t*>(sBh[p] + row + ek + 2 * tig);
                bh1[bt] = *reinterpret_cast<const uint32_t*>(sBh[p] + row + ek + 8 + 2 * tig);
                bl0[bt] = *reinterpret_cast<const uint32_t*>(sBl[p] + row + ek + 2 * tig);
                bl1[bt] = *reinterpret_cast<const uint32_t*>(sBl[p] + row + ek + 8 + 2 * tig);
            }
#pragma unroll
            for (int mt = 0; mt < 2; mt++) {
                const int mb = warp * 32 + mt * 16;
                const int e_loc = ek + kh * 8 + li;
                const uint32_t cc = (uint32_t)((mb >> 3) + half);
                const uint32_t a_off = (uint32_t)e_loc * 256 +
                                       ((cc ^ (uint32_t)(e_loc & 7)) << 4);
                uint32_t a[4];
                ldsm_x4_t(a, s2u(&sA[p][0]) + a_off);
#pragma unroll
                for (int bt = 0; bt < 3; bt++) {
                    hmma(acc[mt][bt], a, bh0[bt], bh1[bt]);
                    hmma(acc[mt][bt], a, bl0[bt], bl1[bt]);
                }
            }
        }
        p ^= 1;
    }

    // ---- epilogue: D fragment -> atomicAdd g_Lv[bc][n] ----
#pragma unroll
    for (int mt = 0; mt < 2; mt++) {
#pragma unroll
        for (int bt = 0; bt < 3; bt++) {
            int n  = n0 + warp * 32 + mt * 16 + g;
            int bc = bt * 8 + 2 * tig;
            atomicAdd(g_Lv + (size_t)bc * NVV + n,           acc[mt][bt][0]);
            atomicAdd(g_Lv + (size_t)(bc + 1) * NVV + n,     acc[mt][bt][1]);
            atomicAdd(g_Lv + (size_t)bc * NVV + n + 8,       acc[mt][bt][2]);
            atomicAdd(g_Lv + (size_t)(bc + 1) * NVV + n + 8, acc[mt][bt][3]);
        }
    }
}

// ---------------------------------------------------------------------------
// Kernel 3: V_predict_new = V_predict + V_w * L_vert
// ---------------------------------------------------------------------------
__global__ void k_epi(const float* __restrict__ Vp,
                      const float* __restrict__ Vw,
                      float*       __restrict__ out)     // (B,NV,3) at d_out
{
    int tid = blockIdx.x * blockDim.x + threadIdx.x;
    if (tid >= BB * NVV) return;
    int b = tid / NVV;
    int n = tid - b * NVV;
    float w = Vw[tid];
    size_t o = (size_t)tid * 3;
    out[o + 0] = Vp[o + 0] + w * g_Lv[(size_t)(b * 3 + 0) * NVV + n];
    out[o + 1] = Vp[o + 1] + w * g_Lv[(size_t)(b * 3 + 1) * NVV + n];
    out[o + 2] = Vp[o + 2] + w * g_Lv[(size_t)(b * 3 + 2) * NVV + n];
}

// ---------------------------------------------------------------------------
extern "C" void kernel_launch(void* const* d_in, const int* in_sizes, int n_in,
                              void* d_out, int out_size)
{
    const float* Vp  = (const float*)d_in[0];   // V_predict    (B,NV,3)
    const float* L   = (const float*)d_in[1];   // L            (B,E,1)
    const float* Vw  = (const float*)d_in[2];   // V_w          (B,NV,1)
    const float* Vc  = (const float*)d_in[3];   // V_compliance (B,1,1)
    const int*   Cd  = (const int*)  d_in[4];   // C_dist       (E,2)
    const float* Cid = (const float*)d_in[5];   // C_init_d     (E,1)
    const float* Cm  = (const float*)d_in[6];   // C_mtx        (E,NV)

    float* out_vp = (float*)d_out;                         // V_predict_new
    float* out_L  = (float*)d_out + (size_t)BB * NVV * 3;  // L_new

    // 1) edge solve -> split-fp16 M, L_new  (+ fused g_Lv zeroing)
    k_edge<<<EDGE_BLOCKS + ZERO_BLOCKS, 256>>>(Vp, L, Vw, Vc, Cd, Cid, out_L);

    // 2) tensor-core GEMM (mma.sync fp16, 2-term emulation, occ 4 - no spills)
    k_gemm_tc<<<dim3(NVV / 128, NSEG), TCT>>>(Cm);

    // 3) vertex update
    k_epi<<<(BB * NVV + 255) / 256, 256>>>(Vp, Vw, out_vp);
}